// round 5
// baseline (speedup 1.0000x reference)
#include <cuda_runtime.h>
#include <math.h>

typedef unsigned int u32;
typedef unsigned long long u64;

#define T_SIZE 524288u
#define T_MASK (T_SIZE - 1u)
#define HPI2 2654435761u
#define HPI3 805459861u
#define MAXN 1048576

__device__ int g_cnt;
__device__ int g_idx[MAXN];
__device__ float4 g_pt[2 * MAXN];  // slot*2+0 = (xc0,xc1,xc2,d0); slot*2+1 = (d1,d2,-,-)

__constant__ float c_NL[16] = {16.f, 22.f, 30.f, 42.f, 58.f, 80.f, 111.f, 153.f,
                               212.f, 293.f, 406.f, 561.f, 775.f, 1071.f, 1481.f, 2046.f};

// ---- weights in constant memory ----
__constant__ ulonglong2 c_dW1v[512];   // 32x64
__constant__ ulonglong2 c_db1v[16];    // 64
__constant__ ulonglong2 c_dW2v[256];   // 64x16
__constant__ ulonglong2 c_db2v[4];     // 16
__constant__ ulonglong2 c_cW1v[688];   // 43x64
__constant__ ulonglong2 c_cb1v[16];    // 64
__constant__ ulonglong2 c_cW2v[1024];  // 64x64
__constant__ ulonglong2 c_cb2v[16];    // 64
__constant__ float      c_cW3[192];    // 64x3
__constant__ float      c_cb3[3];

// ---- f32x2 packed-FMA helpers (sm_103a FFMA2, PTX-only) ----
__device__ __forceinline__ u64 fma2(u64 a, u64 b, u64 c) {
    u64 d;
    asm("fma.rn.f32x2 %0, %1, %2, %3;" : "=l"(d) : "l"(a), "l"(b), "l"(c));
    return d;
}
__device__ __forceinline__ u64 dup2(float v) {
    u64 d;
    asm("mov.b64 %0, {%1, %1};" : "=l"(d) : "f"(v));
    return d;
}
__device__ __forceinline__ float2 unpack2(u64 v) {
    float2 r;
    asm("mov.b64 {%0, %1}, %2;" : "=f"(r.x), "=f"(r.y) : "l"(v));
    return r;
}
__device__ __forceinline__ u64 pack2(float a, float b) {
    u64 d;
    asm("mov.b64 %0, {%1, %2};" : "=l"(d) : "f"(a), "f"(b));
    return d;
}
__device__ __forceinline__ u64 relu2(u64 v) {
    float2 p = unpack2(v);
    return pack2(fmaxf(p.x, 0.0f), fmaxf(p.y, 0.0f));
}

// accumulate v * (32-float row slice, 8 ulonglong2) into 32-wide packed half-accumulator
__device__ __forceinline__ void acc_half(u64 acc[16], u64 dv, const ulonglong2* s) {
    #pragma unroll
    for (int k = 0; k < 8; k++) {
        const ulonglong2 w = s[k];
        acc[2 * k + 0] = fma2(dv, w.x, acc[2 * k + 0]);
        acc[2 * k + 1] = fma2(dv, w.y, acc[2 * k + 1]);
    }
}

// ------------------------------------------------------------------
// Kernel 1: mask, zero dead outputs, compact indices + coords/dirs
// ------------------------------------------------------------------
__global__ __launch_bounds__(256)
void mask_zero_compact(const float* __restrict__ x, const float* __restrict__ dvec,
                       float* __restrict__ out, int n) {
    const int i = blockIdx.x * blockDim.x + threadIdx.x;
    const bool valid = (i < n);
    bool m = false;
    float xs0 = 0.f, xs1 = 0.f, xs2 = 0.f;
    if (valid) {
        xs0 = x[3 * i + 0] * (1.0f / 3.0f);
        xs1 = x[3 * i + 1] * (1.0f / 3.0f);
        xs2 = x[3 * i + 2] * (1.0f / 3.0f);
        m = (fabsf(xs0) < 0.5f) && (fabsf(xs1) < 0.5f) && (fabsf(xs2) < 0.5f);
    }
    const u32 bal = __ballot_sync(0xffffffffu, m);
    const int lane = threadIdx.x & 31;
    int base = 0;
    if (lane == 0 && bal) base = atomicAdd(&g_cnt, __popc(bal));
    base = __shfl_sync(0xffffffffu, base, 0);
    if (m) {
        const int slot = base + __popc(bal & ((1u << lane) - 1u));
        g_idx[slot] = i;
        const float d0 = dvec[3 * i + 0];
        const float d1 = dvec[3 * i + 1];
        const float d2 = dvec[3 * i + 2];
        g_pt[2 * slot + 0] = make_float4(xs0 + 0.5f, xs1 + 0.5f, xs2 + 0.5f, d0);
        g_pt[2 * slot + 1] = make_float4(d1, d2, 0.f, 0.f);
    } else if (valid) {
        out[3 * i + 0] = 0.0f;
        out[3 * i + 1] = 0.0f;
        out[3 * i + 2] = 0.0f;
        out[3 * n + i] = 0.0f;  // exp(-10000) underflows to 0
    }
}

// issue one level's 8 corner gathers (plain LDG, register destination)
__device__ __forceinline__ void hash_fetch(int lev, float xc0, float xc1, float xc2,
                                           const float2* __restrict__ tb2, float2 e[8]) {
    const float nl = c_NL[lev];
    const float xn0 = xc0 * nl, xn1 = xc1 * nl, xn2 = xc2 * nl;
    const u32 f0 = (u32)floorf(xn0), f1 = (u32)floorf(xn1), f2 = (u32)floorf(xn2);
    const u32 cx = (u32)ceilf(xn0), cy = (u32)ceilf(xn1), cz = (u32)ceilf(xn2);
    const u32 hyf = f1 * HPI2, hyc = cy * HPI2;
    const u32 hzf = f2 * HPI3, hzc = cz * HPI3;
    const float2* __restrict__ tl = tb2 + (size_t)lev * T_SIZE;
    #pragma unroll
    for (int v = 0; v < 8; v++) {
        const u32 h = (((v & 1) ? cx : f0)
                     ^ ((v & 2) ? hyc : hyf)
                     ^ ((v & 4) ? hzc : hzf)) & T_MASK;
        e[v] = __ldg(tl + h);
    }
}

// ------------------------------------------------------------------
// Kernel 2: fused NGP forward, TWO THREADS PER POINT (adjacent lanes)
//   sub=0: gathers levels 0-7,  owns outputs [0,32)  of every 64-wide layer
//   sub=1: gathers levels 8-15, owns outputs [32,64)
// ------------------------------------------------------------------
__global__ __launch_bounds__(128, 5)
void ngp_fwd(const float* __restrict__ tables, float* __restrict__ out, int n)
{
    const int cnt = g_cnt;
    if (blockIdx.x * 64 >= cnt) return;                 // uniform block early-exit

    const int t = blockIdx.x * 128 + threadIdx.x;
    const int slot = t >> 1;
    const int sub = t & 1;
    const int ps = (slot < cnt) ? slot : (cnt - 1);     // clamp; keep all lanes active

    const float4 p0 = g_pt[2 * ps + 0];
    const float4 p1 = g_pt[2 * ps + 1];
    const float xc0 = p0.x, xc1 = p0.y, xc2 = p0.z;
    const float d0v = p0.w, d1v = p1.x, d2v = p1.y;

    const float2* __restrict__ tb2 = (const float2*)tables;

    // ---- density layer 1 (32 -> 64), my output half, pair-exchanged features ----
    u64 hh[16];
    #pragma unroll
    for (int j = 0; j < 8; j++) {
        const ulonglong2 b = c_db1v[sub * 8 + j];
        hh[2 * j + 0] = b.x;
        hh[2 * j + 1] = b.y;
    }

    float2 pe[8];
    hash_fetch(sub * 8, xc0, xc1, xc2, tb2, pe);        // my level 0

    #pragma unroll 1
    for (int i = 0; i < 8; i++) {
        const int lev = sub * 8 + i;
        float2 ne[8];
        if (i < 7) hash_fetch(lev + 1, xc0, xc1, xc2, tb2, ne);   // next level in flight

        // trilinear weights for my level
        const float nl = c_NL[lev];
        const float xn0 = xc0 * nl, xn1 = xc1 * nl, xn2 = xc2 * nl;
        const float w0 = xn0 - floorf(xn0);
        const float w1 = xn1 - floorf(xn1);
        const float w2 = xn2 - floorf(xn2);
        const float v0 = 1.0f - w0, v1 = 1.0f - w1, v2 = 1.0f - w2;

        float fa = 0.0f, fb = 0.0f;
        #pragma unroll
        for (int v = 0; v < 8; v++) {
            const float wc = ((v & 1) ? w0 : v0) * ((v & 2) ? w1 : v1) * ((v & 4) ? w2 : v2);
            fa = fmaf(wc, pe[v].x, fa);
            fb = fmaf(wc, pe[v].y, fb);
        }

        // exchange features with partner (same step i, partner holds level (1-sub)*8+i)
        const float ofa = __shfl_xor_sync(0xffffffffu, fa, 1);
        const float ofb = __shfl_xor_sync(0xffffffffu, fb, 1);

        // canonical order: (vA0,vA1)=level-i features (rows 2i,2i+1);
        //                  (vB0,vB1)=level-(8+i) features (rows 16+2i,17+2i)
        const float vA0 = sub ? ofa : fa;
        const float vA1 = sub ? ofb : fb;
        const float vB0 = sub ? fa : ofa;
        const float vB1 = sub ? fb : ofb;

        const int rA = 2 * i;        // feature rows of level i
        const int rB = 16 + 2 * i;   // feature rows of level 8+i
        acc_half(hh, dup2(vA0), c_dW1v + (rA + 0) * 16 + sub * 8);
        acc_half(hh, dup2(vA1), c_dW1v + (rA + 1) * 16 + sub * 8);
        acc_half(hh, dup2(vB0), c_dW1v + (rB + 0) * 16 + sub * 8);
        acc_half(hh, dup2(vB1), c_dW1v + (rB + 1) * 16 + sub * 8);

        #pragma unroll
        for (int v = 0; v < 8; v++) pe[v] = ne[v];
    }

    // relu my half -> 32 scalars (global h1 indices sub*32 + m)
    float a1[32];
    #pragma unroll
    for (int j = 0; j < 16; j++) {
        const float2 p = unpack2(hh[j]);
        a1[2 * j + 0] = fmaxf(p.x, 0.0f);
        a1[2 * j + 1] = fmaxf(p.y, 0.0f);
    }

    // ---- density layer 2 (64 -> 16): partial over my 32 inputs, pair-reduce ----
    u64 p16[8];
    #pragma unroll
    for (int j = 0; j < 4; j++) {
        const ulonglong2 b = c_db2v[j];
        p16[2 * j + 0] = sub ? 0ull : b.x;
        p16[2 * j + 1] = sub ? 0ull : b.y;
    }
    #pragma unroll
    for (int m = 0; m < 32; m++) {
        const u64 dv = dup2(a1[m]);
        const ulonglong2* r = c_dW2v + (sub * 32 + m) * 4;
        #pragma unroll
        for (int j = 0; j < 4; j++) {
            const ulonglong2 w = r[j];
            p16[2 * j + 0] = fma2(dv, w.x, p16[2 * j + 0]);
            p16[2 * j + 1] = fma2(dv, w.y, p16[2 * j + 1]);
        }
    }
    float h16[16];
    #pragma unroll
    for (int j = 0; j < 8; j++) {
        const float2 p = unpack2(p16[j]);
        h16[2 * j + 0] = p.x + __shfl_xor_sync(0xffffffffu, p.x, 1);
        h16[2 * j + 1] = p.y + __shfl_xor_sync(0xffffffffu, p.y, 1);
    }
    const float sigma = __expf(h16[0]);

    // ---- color layer 1 (43 -> 64), my output half ----
    u64 g1[16];
    #pragma unroll
    for (int j = 0; j < 8; j++) {
        const ulonglong2 b = c_cb1v[sub * 8 + j];
        g1[2 * j + 0] = b.x;
        g1[2 * j + 1] = b.y;
    }
    #pragma unroll
    for (int i = 0; i < 16; i++) acc_half(g1, dup2(h16[i]), c_cW1v + i * 16 + sub * 8);
    acc_half(g1, dup2(d0v), c_cW1v + 16 * 16 + sub * 8);
    acc_half(g1, dup2(d1v), c_cW1v + 17 * 16 + sub * 8);
    acc_half(g1, dup2(d2v), c_cW1v + 18 * 16 + sub * 8);
    {
        float f = 1.0f;
        #pragma unroll
        for (int i = 0; i < 4; i++) {
            const float b0 = f * d0v, b1 = f * d1v, b2 = f * d2v;
            const int r = 19 + 6 * i;
            acc_half(g1, dup2(__sinf(b0)), c_cW1v + (r + 0) * 16 + sub * 8);
            acc_half(g1, dup2(__sinf(b1)), c_cW1v + (r + 1) * 16 + sub * 8);
            acc_half(g1, dup2(__sinf(b2)), c_cW1v + (r + 2) * 16 + sub * 8);
            acc_half(g1, dup2(__cosf(b0)), c_cW1v + (r + 3) * 16 + sub * 8);
            acc_half(g1, dup2(__cosf(b1)), c_cW1v + (r + 4) * 16 + sub * 8);
            acc_half(g1, dup2(__cosf(b2)), c_cW1v + (r + 5) * 16 + sub * 8);
            f *= 2.0f;
        }
    }

    // ---- color layer 2 (64 -> 64), my output half; inputs exchanged per slot ----
    u64 g2[16];
    #pragma unroll
    for (int j = 0; j < 8; j++) {
        const ulonglong2 b = c_cb2v[sub * 8 + j];
        g2[2 * j + 0] = b.x;
        g2[2 * j + 1] = b.y;
    }
    #pragma unroll
    for (int k = 0; k < 16; k++) {
        const u64 own = relu2(g1[k]);                     // my slot k (already relu'd)
        const u64 oth = __shfl_xor_sync(0xffffffffu, own, 1);
        // canonical: sE = inputs (2k,2k+1) [even's half], sO = inputs (32+2k,33+2k)
        const u64 sE = sub ? oth : own;
        const u64 sO = sub ? own : oth;
        const float2 eE = unpack2(sE);
        const float2 eO = unpack2(sO);
        acc_half(g2, dup2(eE.x), c_cW2v + (2 * k + 0) * 16 + sub * 8);
        acc_half(g2, dup2(eE.y), c_cW2v + (2 * k + 1) * 16 + sub * 8);
        acc_half(g2, dup2(eO.x), c_cW2v + (32 + 2 * k + 0) * 16 + sub * 8);
        acc_half(g2, dup2(eO.y), c_cW2v + (32 + 2 * k + 1) * 16 + sub * 8);
    }

    // ---- color layer 3 (64 -> 3): partial over my 32 inputs, pair-reduce ----
    float o0 = sub ? 0.0f : c_cb3[0];
    float o1 = sub ? 0.0f : c_cb3[1];
    float o2 = sub ? 0.0f : c_cb3[2];
    #pragma unroll
    for (int j = 0; j < 16; j++) {
        const float2 p = unpack2(g2[j]);
        const float u = fmaxf(p.x, 0.0f);
        const float v = fmaxf(p.y, 0.0f);
        const int i0 = sub * 32 + 2 * j;
        o0 = fmaf(u, c_cW3[i0 * 3 + 0], o0);
        o1 = fmaf(u, c_cW3[i0 * 3 + 1], o1);
        o2 = fmaf(u, c_cW3[i0 * 3 + 2], o2);
        o0 = fmaf(v, c_cW3[i0 * 3 + 3], o0);
        o1 = fmaf(v, c_cW3[i0 * 3 + 4], o1);
        o2 = fmaf(v, c_cW3[i0 * 3 + 5], o2);
    }
    o0 += __shfl_xor_sync(0xffffffffu, o0, 1);
    o1 += __shfl_xor_sync(0xffffffffu, o1, 1);
    o2 += __shfl_xor_sync(0xffffffffu, o2, 1);

    if (sub == 0 && slot < cnt) {
        const int idx = g_idx[ps];
        out[3 * idx + 0] = __fdividef(1.0f, 1.0f + __expf(-o0));
        out[3 * idx + 1] = __fdividef(1.0f, 1.0f + __expf(-o1));
        out[3 * idx + 2] = __fdividef(1.0f, 1.0f + __expf(-o2));
        out[3 * n + idx] = sigma;
    }
}

extern "C" void kernel_launch(void* const* d_in, const int* in_sizes, int n_in,
                              void* d_out, int out_size) {
    const float* x      = (const float*)d_in[0];
    const float* d      = (const float*)d_in[1];
    const float* tables = (const float*)d_in[2];
    float* out = (float*)d_out;
    const int n = in_sizes[0] / 3;

    cudaMemcpyToSymbolAsync(c_dW1v, d_in[3],  2048 * 4, 0, cudaMemcpyDeviceToDevice, 0);
    cudaMemcpyToSymbolAsync(c_db1v, d_in[4],    64 * 4, 0, cudaMemcpyDeviceToDevice, 0);
    cudaMemcpyToSymbolAsync(c_dW2v, d_in[5],  1024 * 4, 0, cudaMemcpyDeviceToDevice, 0);
    cudaMemcpyToSymbolAsync(c_db2v, d_in[6],    16 * 4, 0, cudaMemcpyDeviceToDevice, 0);
    cudaMemcpyToSymbolAsync(c_cW1v, d_in[7],  2752 * 4, 0, cudaMemcpyDeviceToDevice, 0);
    cudaMemcpyToSymbolAsync(c_cb1v, d_in[8],    64 * 4, 0, cudaMemcpyDeviceToDevice, 0);
    cudaMemcpyToSymbolAsync(c_cW2v, d_in[9],  4096 * 4, 0, cudaMemcpyDeviceToDevice, 0);
    cudaMemcpyToSymbolAsync(c_cb2v, d_in[10],   64 * 4, 0, cudaMemcpyDeviceToDevice, 0);
    cudaMemcpyToSymbolAsync(c_cW3,  d_in[11],  192 * 4, 0, cudaMemcpyDeviceToDevice, 0);
    cudaMemcpyToSymbolAsync(c_cb3,  d_in[12],    3 * 4, 0, cudaMemcpyDeviceToDevice, 0);

    void* cnt_addr = nullptr;
    cudaGetSymbolAddress(&cnt_addr, g_cnt);
    cudaMemsetAsync(cnt_addr, 0, sizeof(int), 0);

    mask_zero_compact<<<(n + 255) / 256, 256>>>(x, d, out, n);
    // two threads per point
    ngp_fwd<<<(n + 63) / 64, 128>>>(tables, out, n);
}

// round 6
// speedup vs baseline: 11.2926x; 11.2926x over previous
#include <cuda_runtime.h>
#include <math.h>

typedef unsigned int u32;
typedef unsigned long long u64;

#define T_SIZE 524288u
#define T_MASK (T_SIZE - 1u)
#define HPI2 2654435761u
#define HPI3 805459861u
#define MAXN 1048576

__device__ int g_cnt;
__device__ int g_idx[MAXN];
__device__ float4 g_pt[2 * MAXN];          // slot*2+0 = (xc0,xc1,xc2,d0); slot*2+1 = (d1,d2,-,-)
__device__ float2 g_feat[16 * (size_t)MAXN];  // [lev][slot] interpolated features

__constant__ float c_NL[16] = {16.f, 22.f, 30.f, 42.f, 58.f, 80.f, 111.f, 153.f,
                               212.f, 293.f, 406.f, 561.f, 775.f, 1071.f, 1481.f, 2046.f};

// ---- weights in constant memory (ALL reads warp-uniform -> LDCU broadcast) ----
__constant__ ulonglong2 c_dW1v[512];   // 32x64
__constant__ ulonglong2 c_db1v[16];    // 64
__constant__ ulonglong2 c_dW2v[256];   // 64x16
__constant__ ulonglong2 c_db2v[4];     // 16
__constant__ ulonglong2 c_cW1v[688];   // 43x64
__constant__ ulonglong2 c_cb1v[16];    // 64
__constant__ ulonglong2 c_cW2v[1024];  // 64x64
__constant__ ulonglong2 c_cb2v[16];    // 64
__constant__ float      c_cW3[192];    // 64x3
__constant__ float      c_cb3[3];

// ---- f32x2 packed-FMA helpers (sm_103a FFMA2, PTX-only) ----
__device__ __forceinline__ u64 fma2(u64 a, u64 b, u64 c) {
    u64 d;
    asm("fma.rn.f32x2 %0, %1, %2, %3;" : "=l"(d) : "l"(a), "l"(b), "l"(c));
    return d;
}
__device__ __forceinline__ u64 dup2(float v) {
    u64 d;
    asm("mov.b64 %0, {%1, %1};" : "=l"(d) : "f"(v));
    return d;
}
__device__ __forceinline__ float2 unpack2(u64 v) {
    float2 r;
    asm("mov.b64 {%0, %1}, %2;" : "=f"(r.x), "=f"(r.y) : "l"(v));
    return r;
}

__device__ __forceinline__ void crow64(u64 acc[32], float v, const ulonglong2* row) {
    const u64 dv = dup2(v);
    #pragma unroll
    for (int k = 0; k < 16; k++) {
        const ulonglong2 w = row[k];
        acc[2 * k + 0] = fma2(dv, w.x, acc[2 * k + 0]);
        acc[2 * k + 1] = fma2(dv, w.y, acc[2 * k + 1]);
    }
}

// ------------------------------------------------------------------
// Kernel 1: mask, zero dead outputs, compact indices + coords/dirs
// ------------------------------------------------------------------
__global__ __launch_bounds__(256)
void mask_zero_compact(const float* __restrict__ x, const float* __restrict__ dvec,
                       float* __restrict__ out, int n) {
    const int i = blockIdx.x * blockDim.x + threadIdx.x;
    const bool valid = (i < n);
    bool m = false;
    float xs0 = 0.f, xs1 = 0.f, xs2 = 0.f;
    if (valid) {
        xs0 = x[3 * i + 0] * (1.0f / 3.0f);
        xs1 = x[3 * i + 1] * (1.0f / 3.0f);
        xs2 = x[3 * i + 2] * (1.0f / 3.0f);
        m = (fabsf(xs0) < 0.5f) && (fabsf(xs1) < 0.5f) && (fabsf(xs2) < 0.5f);
    }
    const u32 bal = __ballot_sync(0xffffffffu, m);
    const int lane = threadIdx.x & 31;
    int base = 0;
    if (lane == 0 && bal) base = atomicAdd(&g_cnt, __popc(bal));
    base = __shfl_sync(0xffffffffu, base, 0);
    if (m) {
        const int slot = base + __popc(bal & ((1u << lane) - 1u));
        g_idx[slot] = i;
        const float d0 = dvec[3 * i + 0];
        const float d1 = dvec[3 * i + 1];
        const float d2 = dvec[3 * i + 2];
        g_pt[2 * slot + 0] = make_float4(xs0 + 0.5f, xs1 + 0.5f, xs2 + 0.5f, d0);
        g_pt[2 * slot + 1] = make_float4(d1, d2, 0.f, 0.f);
    } else if (valid) {
        out[3 * i + 0] = 0.0f;
        out[3 * i + 1] = 0.0f;
        out[3 * i + 2] = 0.0f;
        out[3 * n + i] = 0.0f;  // exp(-10000) underflows to 0
    }
}

// ------------------------------------------------------------------
// Kernel 2: hash-grid encode (gather-bound, lightweight -> high occupancy)
//   writes interpolated features to g_feat[lev][slot] (coalesced)
// ------------------------------------------------------------------
__global__ __launch_bounds__(256)
void ngp_encode(const float* __restrict__ tables) {
    const int slot = blockIdx.x * 256 + threadIdx.x;
    if (slot >= g_cnt) return;

    const float4 p0 = g_pt[2 * slot + 0];
    const float xc0 = p0.x, xc1 = p0.y, xc2 = p0.z;
    const float2* __restrict__ tb2 = (const float2*)tables;

    #pragma unroll 2
    for (int lev = 0; lev < 16; lev++) {
        const float nl = c_NL[lev];
        const float xn0 = xc0 * nl, xn1 = xc1 * nl, xn2 = xc2 * nl;
        const float fl0 = floorf(xn0), fl1 = floorf(xn1), fl2 = floorf(xn2);
        const float w0 = xn0 - fl0, w1 = xn1 - fl1, w2 = xn2 - fl2;
        const float v0 = 1.0f - w0, v1 = 1.0f - w1, v2 = 1.0f - w2;
        const u32 f0 = (u32)fl0, f1 = (u32)fl1, f2 = (u32)fl2;
        const u32 cx = (u32)ceilf(xn0), cy = (u32)ceilf(xn1), cz = (u32)ceilf(xn2);
        const u32 hyf = f1 * HPI2, hyc = cy * HPI2;
        const u32 hzf = f2 * HPI3, hzc = cz * HPI3;
        const float2* __restrict__ tl = tb2 + (size_t)lev * T_SIZE;

        float2 e[8];
        #pragma unroll
        for (int v = 0; v < 8; v++) {
            const u32 h = (((v & 1) ? cx : f0)
                         ^ ((v & 2) ? hyc : hyf)
                         ^ ((v & 4) ? hzc : hzf)) & T_MASK;
            e[v] = __ldg(tl + h);
        }
        float fa = 0.0f, fb = 0.0f;
        #pragma unroll
        for (int v = 0; v < 8; v++) {
            const float wc = ((v & 1) ? w0 : v0) * ((v & 2) ? w1 : v1) * ((v & 4) ? w2 : v2);
            fa = fmaf(wc, e[v].x, fa);
            fb = fmaf(wc, e[v].y, fb);
        }
        g_feat[(size_t)lev * MAXN + slot] = make_float2(fa, fb);
    }
}

// ------------------------------------------------------------------
// Kernel 3: MLP chain (fma-bound), 1 thread/point, uniform const weights
// ------------------------------------------------------------------
__global__ __launch_bounds__(128, 4)
void ngp_mlp(float* __restrict__ out, int n) {
    const int slot = blockIdx.x * 128 + threadIdx.x;
    if (slot >= g_cnt) return;
    const int idx = g_idx[slot];

    const float4 p0 = g_pt[2 * slot + 0];
    const float4 p1 = g_pt[2 * slot + 1];
    const float d0v = p0.w, d1v = p1.x, d2v = p1.y;

    // ---- density layer 1 (32 -> 64) from precomputed feats ----
    u64 h1x2[32];
    #pragma unroll
    for (int k = 0; k < 16; k++) {
        const ulonglong2 b = c_db1v[k];
        h1x2[2 * k + 0] = b.x;
        h1x2[2 * k + 1] = b.y;
    }
    #pragma unroll
    for (int lev = 0; lev < 16; lev++) {
        const float2 f = g_feat[(size_t)lev * MAXN + slot];
        const u64 dA = dup2(f.x), dB = dup2(f.y);
        const ulonglong2* Wa = c_dW1v + lev * 32;
        const ulonglong2* Wb = c_dW1v + lev * 32 + 16;
        #pragma unroll
        for (int k = 0; k < 16; k++) {
            const ulonglong2 a = Wa[k];
            const ulonglong2 b = Wb[k];
            h1x2[2 * k + 0] = fma2(dA, a.x, fma2(dB, b.x, h1x2[2 * k + 0]));
            h1x2[2 * k + 1] = fma2(dA, a.y, fma2(dB, b.y, h1x2[2 * k + 1]));
        }
    }

    // ---- density layer 2 (64 -> 16), relu on inputs ----
    u64 h16x2[8];
    #pragma unroll
    for (int j = 0; j < 4; j++) {
        const ulonglong2 b = c_db2v[j];
        h16x2[2 * j + 0] = b.x;
        h16x2[2 * j + 1] = b.y;
    }
    #pragma unroll
    for (int k = 0; k < 32; k++) {
        const float2 p = unpack2(h1x2[k]);
        const u64 d0 = dup2(fmaxf(p.x, 0.0f));
        const u64 d1 = dup2(fmaxf(p.y, 0.0f));
        const ulonglong2* r0 = c_dW2v + (2 * k) * 4;
        const ulonglong2* r1 = r0 + 4;
        #pragma unroll
        for (int j = 0; j < 4; j++) {
            const ulonglong2 A = r0[j];
            const ulonglong2 B = r1[j];
            h16x2[2 * j + 0] = fma2(d0, A.x, fma2(d1, B.x, h16x2[2 * j + 0]));
            h16x2[2 * j + 1] = fma2(d0, A.y, fma2(d1, B.y, h16x2[2 * j + 1]));
        }
    }

    float h16[16];
    #pragma unroll
    for (int j = 0; j < 8; j++) {
        const float2 p = unpack2(h16x2[j]);
        h16[2 * j + 0] = p.x;
        h16[2 * j + 1] = p.y;
    }
    const float sigma = __expf(h16[0]);

    // ---- color layer 1 (43 -> 64), inputs streamed ----
    u64 g1x2[32];
    #pragma unroll
    for (int k = 0; k < 16; k++) {
        const ulonglong2 b = c_cb1v[k];
        g1x2[2 * k + 0] = b.x;
        g1x2[2 * k + 1] = b.y;
    }
    #pragma unroll
    for (int i = 0; i < 16; i++) crow64(g1x2, h16[i], c_cW1v + i * 16);
    crow64(g1x2, d0v, c_cW1v + 16 * 16);
    crow64(g1x2, d1v, c_cW1v + 17 * 16);
    crow64(g1x2, d2v, c_cW1v + 18 * 16);
    {
        float f = 1.0f;
        #pragma unroll
        for (int i = 0; i < 4; i++) {
            const float a0 = f * d0v, a1 = f * d1v, a2 = f * d2v;
            const int r = 19 + 6 * i;
            crow64(g1x2, __sinf(a0), c_cW1v + (r + 0) * 16);
            crow64(g1x2, __sinf(a1), c_cW1v + (r + 1) * 16);
            crow64(g1x2, __sinf(a2), c_cW1v + (r + 2) * 16);
            crow64(g1x2, __cosf(a0), c_cW1v + (r + 3) * 16);
            crow64(g1x2, __cosf(a1), c_cW1v + (r + 4) * 16);
            crow64(g1x2, __cosf(a2), c_cW1v + (r + 5) * 16);
            f *= 2.0f;
        }
    }

    // ---- color layer 2 (64 -> 64) + layer 3 (64 -> 3), two 32-output passes ----
    float o0 = c_cb3[0], o1 = c_cb3[1], o2 = c_cb3[2];
    #pragma unroll
    for (int half = 0; half < 2; half++) {
        u64 g2h[16];
        #pragma unroll
        for (int j = 0; j < 8; j++) {
            const ulonglong2 b = c_cb2v[half * 8 + j];
            g2h[2 * j + 0] = b.x;
            g2h[2 * j + 1] = b.y;
        }
        #pragma unroll
        for (int k = 0; k < 32; k++) {
            const float2 p = unpack2(g1x2[k]);
            const u64 d0 = dup2(fmaxf(p.x, 0.0f));
            const u64 d1 = dup2(fmaxf(p.y, 0.0f));
            const ulonglong2* r0 = c_cW2v + (2 * k) * 16 + half * 8;
            const ulonglong2* r1 = r0 + 16;
            #pragma unroll
            for (int j = 0; j < 8; j++) {
                const ulonglong2 A = r0[j];
                const ulonglong2 B = r1[j];
                g2h[2 * j + 0] = fma2(d0, A.x, fma2(d1, B.x, g2h[2 * j + 0]));
                g2h[2 * j + 1] = fma2(d0, A.y, fma2(d1, B.y, g2h[2 * j + 1]));
            }
        }
        #pragma unroll
        for (int j = 0; j < 16; j++) {
            const float2 p = unpack2(g2h[j]);
            const float a0 = fmaxf(p.x, 0.0f);
            const float a1 = fmaxf(p.y, 0.0f);
            const int i0 = half * 32 + 2 * j;
            o0 = fmaf(a0, c_cW3[i0 * 3 + 0], o0);
            o1 = fmaf(a0, c_cW3[i0 * 3 + 1], o1);
            o2 = fmaf(a0, c_cW3[i0 * 3 + 2], o2);
            o0 = fmaf(a1, c_cW3[i0 * 3 + 3], o0);
            o1 = fmaf(a1, c_cW3[i0 * 3 + 4], o1);
            o2 = fmaf(a1, c_cW3[i0 * 3 + 5], o2);
        }
    }

    out[3 * idx + 0] = __fdividef(1.0f, 1.0f + __expf(-o0));
    out[3 * idx + 1] = __fdividef(1.0f, 1.0f + __expf(-o1));
    out[3 * idx + 2] = __fdividef(1.0f, 1.0f + __expf(-o2));
    out[3 * n + idx] = sigma;
}

extern "C" void kernel_launch(void* const* d_in, const int* in_sizes, int n_in,
                              void* d_out, int out_size) {
    const float* x      = (const float*)d_in[0];
    const float* d      = (const float*)d_in[1];
    const float* tables = (const float*)d_in[2];
    float* out = (float*)d_out;
    const int n = in_sizes[0] / 3;

    cudaMemcpyToSymbolAsync(c_dW1v, d_in[3],  2048 * 4, 0, cudaMemcpyDeviceToDevice, 0);
    cudaMemcpyToSymbolAsync(c_db1v, d_in[4],    64 * 4, 0, cudaMemcpyDeviceToDevice, 0);
    cudaMemcpyToSymbolAsync(c_dW2v, d_in[5],  1024 * 4, 0, cudaMemcpyDeviceToDevice, 0);
    cudaMemcpyToSymbolAsync(c_db2v, d_in[6],    16 * 4, 0, cudaMemcpyDeviceToDevice, 0);
    cudaMemcpyToSymbolAsync(c_cW1v, d_in[7],  2752 * 4, 0, cudaMemcpyDeviceToDevice, 0);
    cudaMemcpyToSymbolAsync(c_cb1v, d_in[8],    64 * 4, 0, cudaMemcpyDeviceToDevice, 0);
    cudaMemcpyToSymbolAsync(c_cW2v, d_in[9],  4096 * 4, 0, cudaMemcpyDeviceToDevice, 0);
    cudaMemcpyToSymbolAsync(c_cb2v, d_in[10],   64 * 4, 0, cudaMemcpyDeviceToDevice, 0);
    cudaMemcpyToSymbolAsync(c_cW3,  d_in[11],  192 * 4, 0, cudaMemcpyDeviceToDevice, 0);
    cudaMemcpyToSymbolAsync(c_cb3,  d_in[12],    3 * 4, 0, cudaMemcpyDeviceToDevice, 0);

    void* cnt_addr = nullptr;
    cudaGetSymbolAddress(&cnt_addr, g_cnt);
    cudaMemsetAsync(cnt_addr, 0, sizeof(int), 0);

    mask_zero_compact<<<(n + 255) / 256, 256>>>(x, d, out, n);
    ngp_encode<<<(n + 255) / 256, 256>>>(tables);
    ngp_mlp<<<(n + 127) / 128, 128>>>(out, n);
}

// round 7
// speedup vs baseline: 12.2378x; 1.0837x over previous
#include <cuda_runtime.h>
#include <math.h>

typedef unsigned int u32;
typedef unsigned long long u64;

#define T_SIZE 524288u
#define T_MASK (T_SIZE - 1u)
#define HPI2 2654435761u
#define HPI3 805459861u
#define MAXN 1048576

__device__ int g_cnt;
__device__ int g_idx[MAXN];
__device__ float4 g_pt[2 * MAXN];             // slot*2+0 = (xc0,xc1,xc2,d0); slot*2+1 = (d1,d2,-,-)
__device__ float2 g_feat[16 * (size_t)MAXN];  // [lev][slot] interpolated features

__constant__ float c_NL[16] = {16.f, 22.f, 30.f, 42.f, 58.f, 80.f, 111.f, 153.f,
                               212.f, 293.f, 406.f, 561.f, 775.f, 1071.f, 1481.f, 2046.f};

// ---- weights in constant memory (ALL reads warp-uniform -> LDCU broadcast) ----
__constant__ ulonglong2 c_dW1v[512];   // 32x64
__constant__ ulonglong2 c_db1v[16];    // 64
__constant__ ulonglong2 c_dW2v[256];   // 64x16
__constant__ ulonglong2 c_db2v[4];     // 16
__constant__ ulonglong2 c_cW1v[688];   // 43x64
__constant__ ulonglong2 c_cb1v[16];    // 64
__constant__ ulonglong2 c_cW2v[1024];  // 64x64
__constant__ ulonglong2 c_cb2v[16];    // 64
__constant__ float      c_cW3[192];    // 64x3
__constant__ float      c_cb3[3];

// ---- f32x2 packed-FMA helpers (sm_103a FFMA2, PTX-only) ----
__device__ __forceinline__ u64 fma2(u64 a, u64 b, u64 c) {
    u64 d;
    asm("fma.rn.f32x2 %0, %1, %2, %3;" : "=l"(d) : "l"(a), "l"(b), "l"(c));
    return d;
}
__device__ __forceinline__ u64 dup2(float v) {
    u64 d;
    asm("mov.b64 %0, {%1, %1};" : "=l"(d) : "f"(v));
    return d;
}
__device__ __forceinline__ float2 unpack2(u64 v) {
    float2 r;
    asm("mov.b64 {%0, %1}, %2;" : "=f"(r.x), "=f"(r.y) : "l"(v));
    return r;
}

__device__ __forceinline__ void crow64(u64 acc[32], float v, const ulonglong2* row) {
    const u64 dv = dup2(v);
    #pragma unroll
    for (int k = 0; k < 16; k++) {
        const ulonglong2 w = row[k];
        acc[2 * k + 0] = fma2(dv, w.x, acc[2 * k + 0]);
        acc[2 * k + 1] = fma2(dv, w.y, acc[2 * k + 1]);
    }
}

// ------------------------------------------------------------------
// Kernel 1: mask, zero dead outputs, compact indices + coords/dirs
// ------------------------------------------------------------------
__global__ __launch_bounds__(256)
void mask_zero_compact(const float* __restrict__ x, const float* __restrict__ dvec,
                       float* __restrict__ out, int n) {
    const int i = blockIdx.x * blockDim.x + threadIdx.x;
    const bool valid = (i < n);
    bool m = false;
    float xs0 = 0.f, xs1 = 0.f, xs2 = 0.f;
    if (valid) {
        xs0 = x[3 * i + 0] * (1.0f / 3.0f);
        xs1 = x[3 * i + 1] * (1.0f / 3.0f);
        xs2 = x[3 * i + 2] * (1.0f / 3.0f);
        m = (fabsf(xs0) < 0.5f) && (fabsf(xs1) < 0.5f) && (fabsf(xs2) < 0.5f);
    }
    const u32 bal = __ballot_sync(0xffffffffu, m);
    const int lane = threadIdx.x & 31;
    int base = 0;
    if (lane == 0 && bal) base = atomicAdd(&g_cnt, __popc(bal));
    base = __shfl_sync(0xffffffffu, base, 0);
    if (m) {
        const int slot = base + __popc(bal & ((1u << lane) - 1u));
        g_idx[slot] = i;
        const float d0 = dvec[3 * i + 0];
        const float d1 = dvec[3 * i + 1];
        const float d2 = dvec[3 * i + 2];
        g_pt[2 * slot + 0] = make_float4(xs0 + 0.5f, xs1 + 0.5f, xs2 + 0.5f, d0);
        g_pt[2 * slot + 1] = make_float4(d1, d2, 0.f, 0.f);
    } else if (valid) {
        out[3 * i + 0] = 0.0f;
        out[3 * i + 1] = 0.0f;
        out[3 * i + 2] = 0.0f;
        out[3 * n + i] = 0.0f;  // exp(-10000) underflows to 0
    }
}

// ------------------------------------------------------------------
// Kernel 2: hash-grid encode; 2 threads/point (8 levels each),
//           x-parity paired LDG.128 gathers where possible
// ------------------------------------------------------------------
__global__ __launch_bounds__(256)
void ngp_encode(const float* __restrict__ tables) {
    const int t = blockIdx.x * 256 + threadIdx.x;
    const int slot = t >> 1;
    if (slot >= g_cnt) return;
    const int half = t & 1;

    const float4 p0 = g_pt[2 * slot + 0];
    const float xc0 = p0.x, xc1 = p0.y, xc2 = p0.z;
    const float2* __restrict__ tb2 = (const float2*)tables;
    const float4* __restrict__ tb4 = (const float4*)tables;

    const int lbase = half * 8;
    #pragma unroll 2
    for (int i = 0; i < 8; i++) {
        const int lev = lbase + i;
        const float nl = c_NL[lev];
        const float xn0 = xc0 * nl, xn1 = xc1 * nl, xn2 = xc2 * nl;
        const float fl0 = floorf(xn0), fl1 = floorf(xn1), fl2 = floorf(xn2);
        const float w0 = xn0 - fl0, w1 = xn1 - fl1, w2 = xn2 - fl2;
        const float v0 = 1.0f - w0, v1 = 1.0f - w1, v2 = 1.0f - w2;
        const u32 f0 = (u32)fl0, f1 = (u32)fl1, f2 = (u32)fl2;
        const u32 cx = (u32)ceilf(xn0), cy = (u32)ceilf(xn1), cz = (u32)ceilf(xn2);
        const u32 hyf = f1 * HPI2, hyc = cy * HPI2;
        const u32 hzf = f2 * HPI3, hzc = cz * HPI3;
        const float2* __restrict__ tl2 = tb2 + (size_t)lev * T_SIZE;
        const float4* __restrict__ tl4 = tb4 + (size_t)lev * (T_SIZE / 2);

        float2 e[8];
        const bool xeven = ((f0 & 1u) == 0u);
        #pragma unroll
        for (int yz = 0; yz < 4; yz++) {
            const u32 rest = ((yz & 1) ? hyc : hyf) ^ ((yz & 2) ? hzc : hzf);
            const u32 h0 = (f0 ^ rest) & T_MASK;
            float2 elo, ehi;
            if (xeven) {
                // corners (f0,...) and (f0+1,...) live at h0 and h0^1: one 16B load.
                // (if xn0 is exactly integer, the x=ceil corner has weight w0=0, so
                //  reading entry f0|1 instead is harmless.)
                const float4 q = __ldg(tl4 + (h0 >> 1));
                if (h0 & 1u) {
                    elo = make_float2(q.z, q.w);
                    ehi = make_float2(q.x, q.y);
                } else {
                    elo = make_float2(q.x, q.y);
                    ehi = make_float2(q.z, q.w);
                }
            } else {
                elo = __ldg(tl2 + h0);
                ehi = __ldg(tl2 + ((cx ^ rest) & T_MASK));
            }
            e[2 * yz + 0] = elo;
            e[2 * yz + 1] = ehi;
        }

        float fa = 0.0f, fb = 0.0f;
        #pragma unroll
        for (int v = 0; v < 8; v++) {
            const float wc = ((v & 1) ? w0 : v0) * ((v & 2) ? w1 : v1) * ((v & 4) ? w2 : v2);
            fa = fmaf(wc, e[v].x, fa);
            fb = fmaf(wc, e[v].y, fb);
        }
        g_feat[(size_t)lev * MAXN + slot] = make_float2(fa, fb);
    }
}

// ------------------------------------------------------------------
// Kernel 3: MLP chain (fma-bound), 1 thread/point, uniform const weights
// ------------------------------------------------------------------
__global__ __launch_bounds__(128, 4)
void ngp_mlp(float* __restrict__ out, int n) {
    const int slot = blockIdx.x * 128 + threadIdx.x;
    if (slot >= g_cnt) return;
    const int idx = g_idx[slot];

    const float4 p0 = g_pt[2 * slot + 0];
    const float4 p1 = g_pt[2 * slot + 1];
    const float d0v = p0.w, d1v = p1.x, d2v = p1.y;

    // ---- density layer 1 (32 -> 64) from precomputed feats ----
    u64 h1x2[32];
    #pragma unroll
    for (int k = 0; k < 16; k++) {
        const ulonglong2 b = c_db1v[k];
        h1x2[2 * k + 0] = b.x;
        h1x2[2 * k + 1] = b.y;
    }
    #pragma unroll
    for (int lev = 0; lev < 16; lev++) {
        const float2 f = g_feat[(size_t)lev * MAXN + slot];
        const u64 dA = dup2(f.x), dB = dup2(f.y);
        const ulonglong2* Wa = c_dW1v + lev * 32;
        const ulonglong2* Wb = c_dW1v + lev * 32 + 16;
        #pragma unroll
        for (int k = 0; k < 16; k++) {
            const ulonglong2 a = Wa[k];
            const ulonglong2 b = Wb[k];
            h1x2[2 * k + 0] = fma2(dA, a.x, fma2(dB, b.x, h1x2[2 * k + 0]));
            h1x2[2 * k + 1] = fma2(dA, a.y, fma2(dB, b.y, h1x2[2 * k + 1]));
        }
    }

    // ---- density layer 2 (64 -> 16), relu on inputs ----
    u64 h16x2[8];
    #pragma unroll
    for (int j = 0; j < 4; j++) {
        const ulonglong2 b = c_db2v[j];
        h16x2[2 * j + 0] = b.x;
        h16x2[2 * j + 1] = b.y;
    }
    #pragma unroll
    for (int k = 0; k < 32; k++) {
        const float2 p = unpack2(h1x2[k]);
        const u64 d0 = dup2(fmaxf(p.x, 0.0f));
        const u64 d1 = dup2(fmaxf(p.y, 0.0f));
        const ulonglong2* r0 = c_dW2v + (2 * k) * 4;
        const ulonglong2* r1 = r0 + 4;
        #pragma unroll
        for (int j = 0; j < 4; j++) {
            const ulonglong2 A = r0[j];
            const ulonglong2 B = r1[j];
            h16x2[2 * j + 0] = fma2(d0, A.x, fma2(d1, B.x, h16x2[2 * j + 0]));
            h16x2[2 * j + 1] = fma2(d0, A.y, fma2(d1, B.y, h16x2[2 * j + 1]));
        }
    }

    float h16[16];
    #pragma unroll
    for (int j = 0; j < 8; j++) {
        const float2 p = unpack2(h16x2[j]);
        h16[2 * j + 0] = p.x;
        h16[2 * j + 1] = p.y;
    }
    const float sigma = __expf(h16[0]);

    // ---- color layer 1 (43 -> 64), inputs streamed ----
    u64 g1x2[32];
    #pragma unroll
    for (int k = 0; k < 16; k++) {
        const ulonglong2 b = c_cb1v[k];
        g1x2[2 * k + 0] = b.x;
        g1x2[2 * k + 1] = b.y;
    }
    #pragma unroll
    for (int i = 0; i < 16; i++) crow64(g1x2, h16[i], c_cW1v + i * 16);
    crow64(g1x2, d0v, c_cW1v + 16 * 16);
    crow64(g1x2, d1v, c_cW1v + 17 * 16);
    crow64(g1x2, d2v, c_cW1v + 18 * 16);
    {
        float f = 1.0f;
        #pragma unroll
        for (int i = 0; i < 4; i++) {
            const float a0 = f * d0v, a1 = f * d1v, a2 = f * d2v;
            const int r = 19 + 6 * i;
            crow64(g1x2, __sinf(a0), c_cW1v + (r + 0) * 16);
            crow64(g1x2, __sinf(a1), c_cW1v + (r + 1) * 16);
            crow64(g1x2, __sinf(a2), c_cW1v + (r + 2) * 16);
            crow64(g1x2, __cosf(a0), c_cW1v + (r + 3) * 16);
            crow64(g1x2, __cosf(a1), c_cW1v + (r + 4) * 16);
            crow64(g1x2, __cosf(a2), c_cW1v + (r + 5) * 16);
            f *= 2.0f;
        }
    }

    // ---- color layer 2 (64 -> 64) + layer 3 (64 -> 3), two 32-output passes ----
    float o0 = c_cb3[0], o1 = c_cb3[1], o2 = c_cb3[2];
    #pragma unroll
    for (int half = 0; half < 2; half++) {
        u64 g2h[16];
        #pragma unroll
        for (int j = 0; j < 8; j++) {
            const ulonglong2 b = c_cb2v[half * 8 + j];
            g2h[2 * j + 0] = b.x;
            g2h[2 * j + 1] = b.y;
        }
        #pragma unroll
        for (int k = 0; k < 32; k++) {
            const float2 p = unpack2(g1x2[k]);
            const u64 d0 = dup2(fmaxf(p.x, 0.0f));
            const u64 d1 = dup2(fmaxf(p.y, 0.0f));
            const ulonglong2* r0 = c_cW2v + (2 * k) * 16 + half * 8;
            const ulonglong2* r1 = r0 + 16;
            #pragma unroll
            for (int j = 0; j < 8; j++) {
                const ulonglong2 A = r0[j];
                const ulonglong2 B = r1[j];
                g2h[2 * j + 0] = fma2(d0, A.x, fma2(d1, B.x, g2h[2 * j + 0]));
                g2h[2 * j + 1] = fma2(d0, A.y, fma2(d1, B.y, g2h[2 * j + 1]));
            }
        }
        #pragma unroll
        for (int j = 0; j < 16; j++) {
            const float2 p = unpack2(g2h[j]);
            const float a0 = fmaxf(p.x, 0.0f);
            const float a1 = fmaxf(p.y, 0.0f);
            const int i0 = half * 32 + 2 * j;
            o0 = fmaf(a0, c_cW3[i0 * 3 + 0], o0);
            o1 = fmaf(a0, c_cW3[i0 * 3 + 1], o1);
            o2 = fmaf(a0, c_cW3[i0 * 3 + 2], o2);
            o0 = fmaf(a1, c_cW3[i0 * 3 + 3], o0);
            o1 = fmaf(a1, c_cW3[i0 * 3 + 4], o1);
            o2 = fmaf(a1, c_cW3[i0 * 3 + 5], o2);
        }
    }

    out[3 * idx + 0] = __fdividef(1.0f, 1.0f + __expf(-o0));
    out[3 * idx + 1] = __fdividef(1.0f, 1.0f + __expf(-o1));
    out[3 * idx + 2] = __fdividef(1.0f, 1.0f + __expf(-o2));
    out[3 * n + idx] = sigma;
}

extern "C" void kernel_launch(void* const* d_in, const int* in_sizes, int n_in,
                              void* d_out, int out_size) {
    const float* x      = (const float*)d_in[0];
    const float* d      = (const float*)d_in[1];
    const float* tables = (const float*)d_in[2];
    float* out = (float*)d_out;
    const int n = in_sizes[0] / 3;

    cudaMemcpyToSymbolAsync(c_dW1v, d_in[3],  2048 * 4, 0, cudaMemcpyDeviceToDevice, 0);
    cudaMemcpyToSymbolAsync(c_db1v, d_in[4],    64 * 4, 0, cudaMemcpyDeviceToDevice, 0);
    cudaMemcpyToSymbolAsync(c_dW2v, d_in[5],  1024 * 4, 0, cudaMemcpyDeviceToDevice, 0);
    cudaMemcpyToSymbolAsync(c_db2v, d_in[6],    16 * 4, 0, cudaMemcpyDeviceToDevice, 0);
    cudaMemcpyToSymbolAsync(c_cW1v, d_in[7],  2752 * 4, 0, cudaMemcpyDeviceToDevice, 0);
    cudaMemcpyToSymbolAsync(c_cb1v, d_in[8],    64 * 4, 0, cudaMemcpyDeviceToDevice, 0);
    cudaMemcpyToSymbolAsync(c_cW2v, d_in[9],  4096 * 4, 0, cudaMemcpyDeviceToDevice, 0);
    cudaMemcpyToSymbolAsync(c_cb2v, d_in[10],   64 * 4, 0, cudaMemcpyDeviceToDevice, 0);
    cudaMemcpyToSymbolAsync(c_cW3,  d_in[11],  192 * 4, 0, cudaMemcpyDeviceToDevice, 0);
    cudaMemcpyToSymbolAsync(c_cb3,  d_in[12],    3 * 4, 0, cudaMemcpyDeviceToDevice, 0);

    void* cnt_addr = nullptr;
    cudaGetSymbolAddress(&cnt_addr, g_cnt);
    cudaMemsetAsync(cnt_addr, 0, sizeof(int), 0);

    mask_zero_compact<<<(n + 255) / 256, 256>>>(x, d, out, n);
    ngp_encode<<<(2 * n + 255) / 256, 256>>>(tables);   // 2 threads per point
    ngp_mlp<<<(n + 127) / 128, 128>>>(out, n);
}